// round 4
// baseline (speedup 1.0000x reference)
#include <cuda_runtime.h>

// Problem dimensions (fixed by the dataset)
#define B_   32
#define T_   4096
#define H_   256
#define S_   256
#define BT_  (B_ * T_)          // 131072 rows
#define CHUNK 256
#define NCH   (T_ / CHUNK)      // 16 chunks

// ---------------------------------------------------------------------------
// Scratch (static __device__ arrays — allocation-free per harness rules)
// ---------------------------------------------------------------------------
__device__ float g_xn[(size_t)BT_ * H_];   // layernormed x        [BT,H]
__device__ float g_u [(size_t)BT_ * S_];   // u, then states (in-place scan) [BT,S]
__device__ float g_mx[(size_t)BT_ * H_];   // gelu(mixed)          [BT,H]
__device__ float g_coeff [S_];
__device__ float g_coeffL[S_];             // coeff^CHUNK
__device__ float g_e     [B_ * NCH * S_];  // chunk-local end states
__device__ float g_carry [B_ * NCH * S_];  // carry_in per chunk

// ---------------------------------------------------------------------------
// Math helpers
// ---------------------------------------------------------------------------
__device__ __forceinline__ float softplus_f(float v) {
    // matches jax.nn.softplus = logaddexp(v, 0)
    return fmaxf(v, 0.f) + log1pf(expf(-fabsf(v)));
}

__device__ __forceinline__ float gelu_tanh(float v) {
    // jax.nn.gelu default: approximate=True (tanh form)
    float t = tanhf(0.7978845608028654f * (v + 0.044715f * v * v * v));
    return 0.5f * v * (1.0f + t);
}

__device__ __forceinline__ unsigned long long dup2(float a) {
    unsigned int u = __float_as_uint(a);
    return ((unsigned long long)u << 32) | (unsigned long long)u;
}
__device__ __forceinline__ unsigned long long pk2(float lo, float hi) {
    return ((unsigned long long)__float_as_uint(hi) << 32) |
           (unsigned long long)__float_as_uint(lo);
}
// Blackwell packed fp32x2 FMA — 2 fp32 FMAs per instruction (sm_100+ PTX)
__device__ __forceinline__ void fma2(unsigned long long& d,
                                     unsigned long long a,
                                     unsigned long long b) {
    asm("fma.rn.f32x2 %0, %1, %2, %0;" : "+l"(d) : "l"(a), "l"(b));
}

// ---------------------------------------------------------------------------
// K0: recurrence coefficients (input-independent)
// ---------------------------------------------------------------------------
__global__ void k_coeff(const float* __restrict__ a_diag,
                        const float* __restrict__ g_diag,
                        const float* __restrict__ dt) {
    int s = threadIdx.x;
    float dts   = softplus_f(dt[s]) + 1e-4f;
    float omega = a_diag[s] * dts;
    float dec   = expf(-softplus_f(g_diag[s]) * dts);
    dec *= dec;                       // damped=True
    float c = dec * cosf(omega);
    g_coeff[s] = c;
    float cl = c;                     // c^(2^8) = c^256 = c^CHUNK
    #pragma unroll
    for (int i = 0; i < 8; i++) cl *= cl;
    g_coeffL[s] = cl;
}

// ---------------------------------------------------------------------------
// K1: LayerNorm per row (warp per row, 8 rows per block)
// ---------------------------------------------------------------------------
__global__ void k_ln(const float* __restrict__ x,
                     const float* __restrict__ w,
                     const float* __restrict__ b) {
    int row  = blockIdx.x * 8 + (threadIdx.x >> 5);
    int lane = threadIdx.x & 31;
    const float* xr = x + (size_t)row * H_;
    float v[8];
    float sum = 0.f;
    #pragma unroll
    for (int i = 0; i < 8; i++) { v[i] = xr[lane + 32 * i]; sum += v[i]; }
    #pragma unroll
    for (int o = 16; o; o >>= 1) sum += __shfl_xor_sync(0xffffffffu, sum, o);
    float mu = sum * (1.f / H_);
    float vs = 0.f;
    #pragma unroll
    for (int i = 0; i < 8; i++) { float d = v[i] - mu; vs += d * d; }
    #pragma unroll
    for (int o = 16; o; o >>= 1) vs += __shfl_xor_sync(0xffffffffu, vs, o);
    float rstd = rsqrtf(vs * (1.f / H_) + 1e-5f);
    float* outr = g_xn + (size_t)row * H_;
    #pragma unroll
    for (int i = 0; i < 8; i++) {
        int col = lane + 32 * i;
        outr[col] = (v[i] - mu) * rstd * w[col] + b[col];
    }
}

// ---------------------------------------------------------------------------
// Tiled NT fp32 GEMM:  C[m,n] = sum_k A[m,k] * W[n,k]   (K = N_total = 256)
// BM=128, BN=128, BK=16, 256 threads, 8x8 microtile via packed f32x2 FMA.
// EPI 0: C = acc                              (u = Win @ xn)
// EPI 1: C = gelu(acc + p0[n]*p1[m,n])        (mixed, p0=direct, p1=xn)
// EPI 2: C = p0[m,n] + acc + p1[n]            (y, p0=x, p1=out_b)
// ---------------------------------------------------------------------------
template <int EPI>
__global__ void __launch_bounds__(256, 2)
k_gemm(const float* __restrict__ A, const float* __restrict__ W,
       float* __restrict__ C,
       const float* __restrict__ p0, const float* __restrict__ p1) {
    __shared__ float As[16][128];
    __shared__ float Bs[16][128];

    int tid = threadIdx.x;
    int tx = tid & 15, ty = tid >> 4;
    size_t mBase = (size_t)blockIdx.y * 128;
    int    nBase = blockIdx.x * 128;
    const float* Ab = A + mBase * 256;
    const float* Wb = W + (size_t)nBase * 256;

    int lr = tid >> 2;          // 0..63
    int lk = (tid & 3) << 2;    // 0,4,8,12

    unsigned long long acc[8][4];
    #pragma unroll
    for (int i = 0; i < 8; i++)
        #pragma unroll
        for (int j = 0; j < 4; j++) acc[i][j] = 0ull;

    for (int kt = 0; kt < 256; kt += 16) {
        float4 a0 = *(const float4*)(Ab + (size_t)lr        * 256 + kt + lk);
        float4 a1 = *(const float4*)(Ab + (size_t)(lr + 64) * 256 + kt + lk);
        float4 b0 = *(const float4*)(Wb + (size_t)lr        * 256 + kt + lk);
        float4 b1 = *(const float4*)(Wb + (size_t)(lr + 64) * 256 + kt + lk);
        __syncthreads();
        As[lk + 0][lr] = a0.x; As[lk + 1][lr] = a0.y;
        As[lk + 2][lr] = a0.z; As[lk + 3][lr] = a0.w;
        As[lk + 0][lr + 64] = a1.x; As[lk + 1][lr + 64] = a1.y;
        As[lk + 2][lr + 64] = a1.z; As[lk + 3][lr + 64] = a1.w;
        Bs[lk + 0][lr] = b0.x; Bs[lk + 1][lr] = b0.y;
        Bs[lk + 2][lr] = b0.z; Bs[lk + 3][lr] = b0.w;
        Bs[lk + 0][lr + 64] = b1.x; Bs[lk + 1][lr + 64] = b1.y;
        Bs[lk + 2][lr + 64] = b1.z; Bs[lk + 3][lr + 64] = b1.w;
        __syncthreads();

        #pragma unroll
        for (int kk = 0; kk < 16; kk++) {
            float4 av0 = *(const float4*)&As[kk][ty * 8];
            float4 av1 = *(const float4*)&As[kk][ty * 8 + 4];
            float4 bv0 = *(const float4*)&Bs[kk][tx * 8];
            float4 bv1 = *(const float4*)&Bs[kk][tx * 8 + 4];
            float av[8] = {av0.x, av0.y, av0.z, av0.w,
                           av1.x, av1.y, av1.z, av1.w};
            unsigned long long bp[4];
            bp[0] = pk2(bv0.x, bv0.y); bp[1] = pk2(bv0.z, bv0.w);
            bp[2] = pk2(bv1.x, bv1.y); bp[3] = pk2(bv1.z, bv1.w);
            #pragma unroll
            for (int i = 0; i < 8; i++) {
                unsigned long long ad = dup2(av[i]);
                #pragma unroll
                for (int j = 0; j < 4; j++) fma2(acc[i][j], ad, bp[j]);
            }
        }
    }

    // Epilogue
    #pragma unroll
    for (int i = 0; i < 8; i++) {
        size_t m = mBase + (size_t)(ty * 8 + i);
        #pragma unroll
        for (int j = 0; j < 4; j++) {
            int n = nBase + tx * 8 + j * 2;
            size_t idx = m * 256 + (size_t)n;
            float lo = __uint_as_float((unsigned)(acc[i][j] & 0xffffffffull));
            float hi = __uint_as_float((unsigned)(acc[i][j] >> 32));
            if (EPI == 0) {
                *(float2*)(C + idx) = make_float2(lo, hi);
            } else if (EPI == 1) {
                lo = gelu_tanh(lo + p0[n]     * p1[idx]);
                hi = gelu_tanh(hi + p0[n + 1] * p1[idx + 1]);
                *(float2*)(C + idx) = make_float2(lo, hi);
            } else {
                lo = p0[idx]     + lo + p1[n];
                hi = p0[idx + 1] + hi + p1[n + 1];
                *(float2*)(C + idx) = make_float2(lo, hi);
            }
        }
    }
}

// ---------------------------------------------------------------------------
// Scan phase 1: chunk-local scan (zero initial), in-place on g_u.
// grid (NCH, B_), 256 threads (one per state channel s).
// ---------------------------------------------------------------------------
__global__ void k_scan1() {
    int s  = threadIdx.x;
    int ch = blockIdx.x;
    int b  = blockIdx.y;
    float c = g_coeff[s];
    size_t base = ((size_t)b * T_ + (size_t)ch * CHUNK) * S_ + s;
    float st = 0.f;
    #pragma unroll 8
    for (int t = 0; t < CHUNK; t++) {
        size_t idx = base + (size_t)t * S_;
        st = fmaf(c, st, g_u[idx]);
        g_u[idx] = st;
    }
    g_e[(b * NCH + ch) * S_ + s] = st;
}

// ---------------------------------------------------------------------------
// Scan phase 2: carry scan across chunks; writes carry_in + final_state.
// ---------------------------------------------------------------------------
__global__ void k_scan2(const float* __restrict__ state0, float* fs_out) {
    int s = threadIdx.x;
    int b = blockIdx.x;
    float cl  = g_coeffL[s];
    float Sin = state0[b * S_ + s];
    #pragma unroll
    for (int ch = 0; ch < NCH; ch++) {
        int e = (b * NCH + ch) * S_ + s;
        g_carry[e] = Sin;
        Sin = fmaf(cl, Sin, g_e[e]);
    }
    if (fs_out) fs_out[b * S_ + s] = Sin;
}

// ---------------------------------------------------------------------------
// Scan phase 3: correction  states[t] += coeff^(t+1) * carry_in
// ---------------------------------------------------------------------------
__global__ void k_scan3() {
    int s  = threadIdx.x;
    int ch = blockIdx.x;
    int b  = blockIdx.y;
    float c     = g_coeff[s];
    float carry = g_carry[(b * NCH + ch) * S_ + s];
    float cp = c;
    size_t base = ((size_t)b * T_ + (size_t)ch * CHUNK) * S_ + s;
    #pragma unroll 8
    for (int t = 0; t < CHUNK; t++) {
        size_t idx = base + (size_t)t * S_;
        g_u[idx] = fmaf(cp, carry, g_u[idx]);
        cp *= c;
    }
}

// ---------------------------------------------------------------------------
// Launch
// ---------------------------------------------------------------------------
extern "C" void kernel_launch(void* const* d_in, const int* in_sizes, int n_in,
                              void* d_out, int out_size) {
    const float* x      = (const float*)d_in[0];
    const float* state0 = (const float*)d_in[1];
    const float* Win    = (const float*)d_in[2];   // [S,H]
    const float* Wsh    = (const float*)d_in[3];   // [H,S]
    const float* direct = (const float*)d_in[4];   // [H]
    const float* a_diag = (const float*)d_in[5];
    const float* g_diag = (const float*)d_in[6];
    const float* dt     = (const float*)d_in[7];
    const float* nw     = (const float*)d_in[8];
    const float* nb     = (const float*)d_in[9];
    const float* ow     = (const float*)d_in[10];  // [H,H]
    const float* ob     = (const float*)d_in[11];
    float* out = (float*)d_out;

    float *xn, *u, *mx;
    cudaGetSymbolAddress((void**)&xn, g_xn);
    cudaGetSymbolAddress((void**)&u,  g_u);
    cudaGetSymbolAddress((void**)&mx, g_mx);

    k_coeff<<<1, S_>>>(a_diag, g_diag, dt);
    k_ln<<<BT_ / 8, 256>>>(x, nw, nb);

    // u = xn @ Win^T
    k_gemm<0><<<dim3(S_ / 128, BT_ / 128), 256>>>(xn, Win, u, nullptr, nullptr);

    // diagonal linear recurrence (chunked parallel scan)
    k_scan1<<<dim3(NCH, B_), 256>>>();
    float* fs_out = ((size_t)out_size >= (size_t)BT_ * H_ + (size_t)B_ * S_)
                        ? out + (size_t)BT_ * H_ : nullptr;
    k_scan2<<<B_, 256>>>(state0, fs_out);
    k_scan3<<<dim3(NCH, B_), 256>>>();

    // mixed = gelu(states @ Wsh^T + direct * xn)
    k_gemm<1><<<dim3(H_ / 128, BT_ / 128), 256>>>(u, Wsh, mx, direct, xn);

    // y = x + mixed @ ow^T + ob
    k_gemm<2><<<dim3(H_ / 128, BT_ / 128), 256>>>(mx, ow, out, x, ob);
}

// round 8
// speedup vs baseline: 2.8085x; 2.8085x over previous
#include <cuda_runtime.h>
#include <cuda_bf16.h>
#include <cstdint>

// Problem dimensions (fixed by the dataset)
#define B_   32
#define T_   4096
#define H_   256
#define S_   256
#define BT_  (B_ * T_)          // 131072 rows
#define CHUNK 256
#define NCH   (T_ / CHUNK)      // 16 chunks

// ---------------------------------------------------------------------------
// Scratch (static __device__ arrays — allocation-free per harness rules)
// ---------------------------------------------------------------------------
__device__ float g_xn[(size_t)BT_ * H_];   // layernormed x        [BT,H]
__device__ float g_u [(size_t)BT_ * S_];   // u, then states (in-place scan) [BT,S]
__device__ float g_mx[(size_t)BT_ * H_];   // gelu(mixed)          [BT,H]
__device__ float g_coeff [S_];
__device__ float g_coeffL[S_];             // coeff^CHUNK
__device__ float g_e     [B_ * NCH * S_];  // chunk-local end states
__device__ float g_carry [B_ * NCH * S_];  // carry_in per chunk
__device__ __nv_bfloat16 g_whi[3 * H_ * H_];  // weights split hi (Win,Wsh,ow)
__device__ __nv_bfloat16 g_wlo[3 * H_ * H_];  // weights split lo

// ---------------------------------------------------------------------------
// Math helpers
// ---------------------------------------------------------------------------
__device__ __forceinline__ float softplus_f(float v) {
    return fmaxf(v, 0.f) + log1pf(expf(-fabsf(v)));
}
__device__ __forceinline__ float gelu_tanh(float v) {
    float t = tanhf(0.7978845608028654f * (v + 0.044715f * v * v * v));
    return 0.5f * v * (1.0f + t);
}
__device__ __forceinline__ uint32_t smem_u32(const void* p) {
    uint32_t a;
    asm("{ .reg .u64 t; cvta.to.shared.u64 t, %1; cvt.u32.u64 %0, t; }"
        : "=r"(a) : "l"(p));
    return a;
}

// ---------------------------------------------------------------------------
// mma.sync / ldmatrix helpers (base sm_80+ PTX — no 'a'-features)
// ---------------------------------------------------------------------------
__device__ __forceinline__ void ldsm4(uint32_t* r, uint32_t a) {
    asm volatile("ldmatrix.sync.aligned.m8n8.x4.shared.b16 {%0,%1,%2,%3}, [%4];"
                 : "=r"(r[0]), "=r"(r[1]), "=r"(r[2]), "=r"(r[3]) : "r"(a));
}
__device__ __forceinline__ void mma16816(float* c, const uint32_t* a,
                                         uint32_t b0, uint32_t b1) {
    asm volatile(
        "mma.sync.aligned.m16n8k16.row.col.f32.bf16.bf16.f32 "
        "{%0,%1,%2,%3}, {%4,%5,%6,%7}, {%8,%9}, {%0,%1,%2,%3};"
        : "+f"(c[0]), "+f"(c[1]), "+f"(c[2]), "+f"(c[3])
        : "r"(a[0]), "r"(a[1]), "r"(a[2]), "r"(a[3]), "r"(b0), "r"(b1));
}

// Convert float4 -> bf16 hi/lo pairs and store 8B each
__device__ __forceinline__ void split_store(float4 v, char* ph, char* pl) {
    __nv_bfloat162 h0 = __floats2bfloat162_rn(v.x, v.y);
    __nv_bfloat162 h1 = __floats2bfloat162_rn(v.z, v.w);
    float rx = v.x - __bfloat162float(h0.x);
    float ry = v.y - __bfloat162float(h0.y);
    float rz = v.z - __bfloat162float(h1.x);
    float rw = v.w - __bfloat162float(h1.y);
    __nv_bfloat162 l0 = __floats2bfloat162_rn(rx, ry);
    __nv_bfloat162 l1 = __floats2bfloat162_rn(rz, rw);
    *(uint2*)ph = make_uint2(*(uint32_t*)&h0, *(uint32_t*)&h1);
    *(uint2*)pl = make_uint2(*(uint32_t*)&l0, *(uint32_t*)&l1);
}

// ---------------------------------------------------------------------------
// K0: recurrence coefficients
// ---------------------------------------------------------------------------
__global__ void k_coeff(const float* __restrict__ a_diag,
                        const float* __restrict__ g_diag,
                        const float* __restrict__ dt) {
    int s = threadIdx.x;
    float dts   = softplus_f(dt[s]) + 1e-4f;
    float omega = a_diag[s] * dts;
    float dec   = expf(-softplus_f(g_diag[s]) * dts);
    dec *= dec;
    float c = dec * cosf(omega);
    g_coeff[s] = c;
    float cl = c;
    #pragma unroll
    for (int i = 0; i < 8; i++) cl *= cl;   // c^256
    g_coeffL[s] = cl;
}

// ---------------------------------------------------------------------------
// K0b: pre-split the three weight matrices into bf16 hi/lo (each 256x256)
// ---------------------------------------------------------------------------
__global__ void k_wsplit(const float* __restrict__ W0,
                         const float* __restrict__ W1,
                         const float* __restrict__ W2) {
    int id = blockIdx.x * 256 + threadIdx.x;      // grid 768
    int w = id >> 16, e = id & 65535;
    const float* src = (w == 0) ? W0 : (w == 1) ? W1 : W2;
    float v = src[e];
    __nv_bfloat16 h = __float2bfloat16_rn(v);
    g_whi[id] = h;
    g_wlo[id] = __float2bfloat16_rn(v - __bfloat162float(h));
}

// ---------------------------------------------------------------------------
// K1: LayerNorm per row (warp per row, 8 rows per block)
// ---------------------------------------------------------------------------
__global__ void k_ln(const float* __restrict__ x,
                     const float* __restrict__ w,
                     const float* __restrict__ b) {
    int row  = blockIdx.x * 8 + (threadIdx.x >> 5);
    int lane = threadIdx.x & 31;
    const float* xr = x + (size_t)row * H_;
    float v[8];
    float sum = 0.f;
    #pragma unroll
    for (int i = 0; i < 8; i++) { v[i] = xr[lane + 32 * i]; sum += v[i]; }
    #pragma unroll
    for (int o = 16; o; o >>= 1) sum += __shfl_xor_sync(0xffffffffu, sum, o);
    float mu = sum * (1.f / H_);
    float vs = 0.f;
    #pragma unroll
    for (int i = 0; i < 8; i++) { float d = v[i] - mu; vs += d * d; }
    #pragma unroll
    for (int o = 16; o; o >>= 1) vs += __shfl_xor_sync(0xffffffffu, vs, o);
    float rstd = rsqrtf(vs * (1.f / H_) + 1e-5f);
    float* outr = g_xn + (size_t)row * H_;
    #pragma unroll
    for (int i = 0; i < 8; i++) {
        int col = lane + 32 * i;
        outr[col] = (v[i] - mu) * rstd * w[col] + b[col];
    }
}

// ---------------------------------------------------------------------------
// bf16-split NT GEMM via mma.sync:  C[m,n] = sum_k A[m,k] * W[n,k]
// BM=128 (per CTA), BN=256 (full N), BK=32, 512 threads (16 warps, 2m x 8n,
// warp tile 64x32). A converted fp32->bf16 hi/lo on the fly; W pre-split.
// fp32 recovered as hh + hl + lh (lo*lo dropped, ~2^-18).
// EPI 0: C = acc
// EPI 1: C = gelu(acc + p0[n]*p1[m,n])
// EPI 2: C = p0[m,n] + acc + p1[n]
// ---------------------------------------------------------------------------
#define ROWB 80                 // smem bytes per 32-bf16 row (16B pad)
#define SM_AH 0
#define SM_AL 10240
#define SM_BH 20480
#define SM_BL 40960
#define SM_TOT 61440

template <int EPI>
__global__ void __launch_bounds__(512)
k_gemm_mma(const float* __restrict__ A,
           const __nv_bfloat16* __restrict__ Wh,
           const __nv_bfloat16* __restrict__ Wl,
           float* __restrict__ C,
           const float* __restrict__ p0,
           const float* __restrict__ p1) {
    extern __shared__ __align__(128) char sm[];
    int tid = threadIdx.x, lane = tid & 31, wid = tid >> 5;
    int wm = wid >> 3, wn = wid & 7;        // 2 x 8 warp grid
    size_t mBase = (size_t)blockIdx.x * 128;
    const float* Ab = A + mBase * 256;

    // prefetch chunk 0 (A: 2 float4/thread; B: 2 uint4 hi + 2 lo)
    float4 ra[2];
    uint4 rbh[2], rbl[2];
    #pragma unroll
    for (int i = 0; i < 2; i++) {
        int idx = tid + 512 * i;
        ra[i] = *(const float4*)(Ab + (size_t)(idx >> 3) * 256 + ((idx & 7) << 2));
    }
    #pragma unroll
    for (int i = 0; i < 2; i++) {
        int idx = tid + 512 * i;                 // row = idx>>2 (0..255), q = idx&3
        rbh[i] = *(const uint4*)(Wh + (idx >> 2) * 256 + ((idx & 3) << 3));
        rbl[i] = *(const uint4*)(Wl + (idx >> 2) * 256 + ((idx & 3) << 3));
    }

    float acc[4][4][4];
    #pragma unroll
    for (int a = 0; a < 4; a++)
        #pragma unroll
        for (int b = 0; b < 4; b++)
            #pragma unroll
            for (int c = 0; c < 4; c++) acc[a][b][c] = 0.f;

    uint32_t sb = smem_u32(sm);
    uint32_t aAddr = sb + SM_AH + (wm * 64 + (lane & 15)) * ROWB + ((lane >> 4) << 4);
    uint32_t bAddr = sb + SM_BH + (wn * 32 + (lane & 15)) * ROWB + ((lane >> 4) << 4);

    for (int ch = 0; ch < 8; ch++) {
        if (ch) __syncthreads();
        #pragma unroll
        for (int i = 0; i < 2; i++) {
            int idx = tid + 512 * i;
            int off = (idx >> 3) * ROWB + (idx & 7) * 8;
            split_store(ra[i], sm + SM_AH + off, sm + SM_AL + off);
        }
        #pragma unroll
        for (int i = 0; i < 2; i++) {
            int idx = tid + 512 * i;
            int off = (idx >> 2) * ROWB + ((idx & 3) << 4);
            *(uint4*)(sm + SM_BH + off) = rbh[i];
            *(uint4*)(sm + SM_BL + off) = rbl[i];
        }
        __syncthreads();

        if (ch < 7) {                            // prefetch next chunk
            int kt = (ch + 1) * 32;
            #pragma unroll
            for (int i = 0; i < 2; i++) {
                int idx = tid + 512 * i;
                ra[i] = *(const float4*)(Ab + (size_t)(idx >> 3) * 256 + kt + ((idx & 7) << 2));
            }
            #pragma unroll
            for (int i = 0; i < 2; i++) {
                int idx = tid + 512 * i;
                rbh[i] = *(const uint4*)(Wh + (idx >> 2) * 256 + kt + ((idx & 3) << 3));
                rbl[i] = *(const uint4*)(Wl + (idx >> 2) * 256 + kt + ((idx & 3) << 3));
            }
        }

        #pragma unroll
        for (int ks = 0; ks < 2; ks++) {
            uint32_t kO = ks * 32;
            uint32_t bh[8], bl[8];
            ldsm4(bh,     bAddr + kO);
            ldsm4(bh + 4, bAddr + 16 * ROWB + kO);
            ldsm4(bl,     bAddr + (SM_BL - SM_BH) + kO);
            ldsm4(bl + 4, bAddr + (SM_BL - SM_BH) + 16 * ROWB + kO);
            #pragma unroll
            for (int mt = 0; mt < 4; mt++) {
                uint32_t ah[4], al[4];
                ldsm4(ah, aAddr + mt * 16 * ROWB + kO);
                ldsm4(al, aAddr + (SM_AL - SM_AH) + mt * 16 * ROWB + kO);
                #pragma unroll
                for (int nt = 0; nt < 4; nt++) {
                    int g = (nt >> 1) * 4, s2 = nt & 1;
                    mma16816(acc[mt][nt], ah, bh[g + s2], bh[g + s2 + 2]);
                    mma16816(acc[mt][nt], ah, bl[g + s2], bl[g + s2 + 2]);
                    mma16816(acc[mt][nt], al, bh[g + s2], bh[g + s2 + 2]);
                }
            }
        }
    }

    // Epilogue: c0,c1 at (m, n..n+1); c2,c3 at (m+8, n..n+1)
    #pragma unroll
    for (int mt = 0; mt < 4; mt++) {
        size_t m0 = mBase + (size_t)(wm * 64 + mt * 16 + (lane >> 2));
        #pragma unroll
        for (int nt = 0; nt < 4; nt++) {
            int n = wn * 32 + nt * 8 + (lane & 3) * 2;
            #pragma unroll
            for (int h = 0; h < 2; h++) {
                size_t m = m0 + h * 8;
                size_t idx = m * 256 + (size_t)n;
                float v0 = acc[mt][nt][h * 2], v1 = acc[mt][nt][h * 2 + 1];
                float2 o;
                if (EPI == 0) {
                    o = make_float2(v0, v1);
                } else if (EPI == 1) {
                    o.x = gelu_tanh(v0 + p0[n]     * p1[idx]);
                    o.y = gelu_tanh(v1 + p0[n + 1] * p1[idx + 1]);
                } else {
                    o.x = p0[idx]     + v0 + p1[n];
                    o.y = p0[idx + 1] + v1 + p1[n + 1];
                }
                *(float2*)(C + idx) = o;
            }
        }
    }
}

// ---------------------------------------------------------------------------
// Scan phase 1: chunk-local scan (zero initial), in-place on g_u.
// ---------------------------------------------------------------------------
__global__ void k_scan1() {
    int s  = threadIdx.x;
    int ch = blockIdx.x;
    int b  = blockIdx.y;
    float c = g_coeff[s];
    size_t base = ((size_t)b * T_ + (size_t)ch * CHUNK) * S_ + s;
    float st = 0.f;
    #pragma unroll 8
    for (int t = 0; t < CHUNK; t++) {
        size_t idx = base + (size_t)t * S_;
        st = fmaf(c, st, g_u[idx]);
        g_u[idx] = st;
    }
    g_e[(b * NCH + ch) * S_ + s] = st;
}

// ---------------------------------------------------------------------------
// Scan phase 2: carry scan across chunks; writes carry_in + final_state.
// ---------------------------------------------------------------------------
__global__ void k_scan2(const float* __restrict__ state0, float* fs_out) {
    int s = threadIdx.x;
    int b = blockIdx.x;
    float cl  = g_coeffL[s];
    float Sin = state0[b * S_ + s];
    #pragma unroll
    for (int ch = 0; ch < NCH; ch++) {
        int e = (b * NCH + ch) * S_ + s;
        g_carry[e] = Sin;
        Sin = fmaf(cl, Sin, g_e[e]);
    }
    if (fs_out) fs_out[b * S_ + s] = Sin;
}

// ---------------------------------------------------------------------------
// Scan phase 3: correction  states[t] += coeff^(t+1) * carry_in
// ---------------------------------------------------------------------------
__global__ void k_scan3() {
    int s  = threadIdx.x;
    int ch = blockIdx.x;
    int b  = blockIdx.y;
    float c     = g_coeff[s];
    float carry = g_carry[(b * NCH + ch) * S_ + s];
    float cp = c;
    size_t base = ((size_t)b * T_ + (size_t)ch * CHUNK) * S_ + s;
    #pragma unroll 8
    for (int t = 0; t < CHUNK; t++) {
        size_t idx = base + (size_t)t * S_;
        g_u[idx] = fmaf(cp, carry, g_u[idx]);
        cp *= c;
    }
}

// ---------------------------------------------------------------------------
// Launch
// ---------------------------------------------------------------------------
extern "C" void kernel_launch(void* const* d_in, const int* in_sizes, int n_in,
                              void* d_out, int out_size) {
    const float* x      = (const float*)d_in[0];
    const float* state0 = (const float*)d_in[1];
    const float* Win    = (const float*)d_in[2];   // [S,H]
    const float* Wsh    = (const float*)d_in[3];   // [H,S]
    const float* direct = (const float*)d_in[4];   // [H]
    const float* a_diag = (const float*)d_in[5];
    const float* g_diag = (const float*)d_in[6];
    const float* dt     = (const float*)d_in[7];
    const float* nw     = (const float*)d_in[8];
    const float* nb     = (const float*)d_in[9];
    const float* ow     = (const float*)d_in[10];  // [H,H]
    const float* ob     = (const float*)d_in[11];
    float* out = (float*)d_out;

    float *xn, *u, *mx;
    __nv_bfloat16 *wh, *wl;
    cudaGetSymbolAddress((void**)&xn, g_xn);
    cudaGetSymbolAddress((void**)&u,  g_u);
    cudaGetSymbolAddress((void**)&mx, g_mx);
    cudaGetSymbolAddress((void**)&wh, g_whi);
    cudaGetSymbolAddress((void**)&wl, g_wlo);

    cudaFuncSetAttribute(k_gemm_mma<0>, cudaFuncAttributeMaxDynamicSharedMemorySize, SM_TOT);
    cudaFuncSetAttribute(k_gemm_mma<1>, cudaFuncAttributeMaxDynamicSharedMemorySize, SM_TOT);
    cudaFuncSetAttribute(k_gemm_mma<2>, cudaFuncAttributeMaxDynamicSharedMemorySize, SM_TOT);

    k_coeff<<<1, S_>>>(a_diag, g_diag, dt);
    k_wsplit<<<768, 256>>>(Win, Wsh, ow);
    k_ln<<<BT_ / 8, 256>>>(x, nw, nb);

    // u = xn @ Win^T
    k_gemm_mma<0><<<BT_ / 128, 512, SM_TOT>>>(xn, wh, wl, u, nullptr, nullptr);

    // diagonal linear recurrence (chunked parallel scan)
    k_scan1<<<dim3(NCH, B_), 256>>>();
    float* fs_out = ((size_t)out_size >= (size_t)BT_ * H_ + (size_t)B_ * S_)
                        ? out + (size_t)BT_ * H_ : nullptr;
    k_scan2<<<B_, 256>>>(state0, fs_out);
    k_scan3<<<dim3(NCH, B_), 256>>>();

    // mixed = gelu(states @ Wsh^T + direct * xn)
    k_gemm_mma<1><<<BT_ / 128, 512, SM_TOT>>>(u, wh + 65536, wl + 65536, mx, direct, xn);

    // y = x + mixed @ ow^T + ob
    k_gemm_mma<2><<<BT_ / 128, 512, SM_TOT>>>(mx, wh + 131072, wl + 131072, out, x, ob);
}